// round 1
// baseline (speedup 1.0000x reference)
#include <cuda_runtime.h>
#include <cstdint>

// Edge-MLP: out[e] = sigmoid( relu( concat(x[row[e]], x[col[e]]) @ W1 + b1 ) @ W2 + b2 )
// x: [50000,128] f32, edge_index: [2,E] i32, W1: [256,64], b1:[64], W2:[64,1], b2:[1]
//
// Strategy: 1 thread = 1 edge. 64 hidden accumulators kept as 32 packed f32x2
// registers, updated with Blackwell packed fma.rn.f32x2 (2 fp32 FMA / issue).
// W1 (64KB) staged to shared (pure broadcast reads). x gathered via float4 with
// 1-deep prefetch to hide L2 latency (x fits in L2 entirely).

#define NODE_DIM 128
#define HID      64
#define HID2     32   // packed pairs

__device__ __forceinline__ unsigned long long pack2(float v) {
    unsigned long long r;
    asm("mov.b64 %0, {%1, %1};" : "=l"(r) : "r"(__float_as_uint(v)));
    return r;
}

__device__ __forceinline__ void fma2(unsigned long long& d,
                                     unsigned long long a,
                                     unsigned long long b) {
    // d = a * b + d  (two fp32 lanes)
    asm("fma.rn.f32x2 %0, %1, %2, %0;" : "+l"(d) : "l"(a), "l"(b));
}

__global__ __launch_bounds__(256, 2)
void edge_mlp_kernel(const float* __restrict__ x,
                     const int*   __restrict__ ei,
                     const float* __restrict__ W1,
                     const float* __restrict__ b1,
                     const float* __restrict__ W2,
                     const float* __restrict__ b2,
                     float* __restrict__ out,
                     int E) {
    extern __shared__ float sm[];
    float* sW1 = sm;                       // 256*64 = 16384 floats (64KB)
    float* sW2 = sm + NODE_DIM * 2 * HID;  // 64
    float* sB1 = sW2 + HID;                // 64

    // Cooperative stage of weights into shared
    {
        float4* d4 = (float4*)sW1;
        const float4* s4 = (const float4*)W1;
        const int n4 = NODE_DIM * 2 * HID / 4;   // 4096
        for (int i = threadIdx.x; i < n4; i += blockDim.x) d4[i] = s4[i];
        if (threadIdx.x < HID) {
            sW2[threadIdx.x] = W2[threadIdx.x];
            sB1[threadIdx.x] = b1[threadIdx.x];
        }
    }
    __syncthreads();

    int e = blockIdx.x * blockDim.x + threadIdx.x;
    if (e >= E) return;

    int r0 = ei[e];
    int r1 = ei[E + e];

    unsigned long long acc[HID2];
    {
        const unsigned long long* b1u = (const unsigned long long*)sB1;
        #pragma unroll
        for (int j = 0; j < HID2; j++) acc[j] = b1u[j];
    }

    #pragma unroll
    for (int ep = 0; ep < 2; ep++) {
        const float4* xr =
            (const float4*)(x + (size_t)(ep ? r1 : r0) * NODE_DIM);
        // W1 rows for this endpoint, viewed as packed f32x2
        const unsigned long long* wb =
            (const unsigned long long*)(sW1 + ep * NODE_DIM * HID);

        float4 xv = xr[0];
        #pragma unroll 1
        for (int k0 = 0; k0 < NODE_DIM / 4; k0++) {
            // prefetch next float4 of gathered x to hide L2 latency
            float4 nxt = xv;
            if (k0 < NODE_DIM / 4 - 1) nxt = xr[k0 + 1];

            const unsigned long long* wk = wb + k0 * 4 * HID2;

            unsigned long long xx;
            xx = pack2(xv.x);
            #pragma unroll
            for (int j = 0; j < HID2; j++) fma2(acc[j], wk[0 * HID2 + j], xx);
            xx = pack2(xv.y);
            #pragma unroll
            for (int j = 0; j < HID2; j++) fma2(acc[j], wk[1 * HID2 + j], xx);
            xx = pack2(xv.z);
            #pragma unroll
            for (int j = 0; j < HID2; j++) fma2(acc[j], wk[2 * HID2 + j], xx);
            xx = pack2(xv.w);
            #pragma unroll
            for (int j = 0; j < HID2; j++) fma2(acc[j], wk[3 * HID2 + j], xx);

            xv = nxt;
        }
    }

    // Epilogue: relu -> dot W2 -> + b2 -> sigmoid
    float z = b2[0];
    #pragma unroll
    for (int j = 0; j < HID2; j++) {
        unsigned int lo, hi;
        asm("mov.b64 {%0, %1}, %2;" : "=r"(lo), "=r"(hi) : "l"(acc[j]));
        float a = fmaxf(__uint_as_float(lo), 0.0f);
        float b = fmaxf(__uint_as_float(hi), 0.0f);
        z = fmaf(a, sW2[2 * j],     z);
        z = fmaf(b, sW2[2 * j + 1], z);
    }
    out[e] = 1.0f / (1.0f + __expf(-z));
}

extern "C" void kernel_launch(void* const* d_in, const int* in_sizes, int n_in,
                              void* d_out, int out_size) {
    const float* x  = (const float*)d_in[0];
    const int*   ei = (const int*)  d_in[1];
    const float* W1 = (const float*)d_in[2];
    const float* b1 = (const float*)d_in[3];
    const float* W2 = (const float*)d_in[4];
    const float* b2 = (const float*)d_in[5];
    float* out = (float*)d_out;

    const int E = out_size;  // one output per edge

    const size_t smem = (NODE_DIM * 2 * HID + 2 * HID + 16) * sizeof(float); // ~66KB
    cudaFuncSetAttribute(edge_mlp_kernel,
                         cudaFuncAttributeMaxDynamicSharedMemorySize,
                         (int)smem);

    const int threads = 256;
    const int blocks  = (E + threads - 1) / threads;
    edge_mlp_kernel<<<blocks, threads, smem>>>(x, ei, W1, b1, W2, b2, out, E);
}

// round 3
// speedup vs baseline: 2.4290x; 2.4290x over previous
#include <cuda_runtime.h>
#include <cuda_bf16.h>
#include <cstdint>

// Edge-MLP: out[e] = sigmoid( relu( concat(x[r],x[c]) @ W1 + b1 ) @ W2 + b2 )
// Tensor-core GEMM (E x 256)@(256 x 64) via mma.sync m16n8k16 bf16 (portable
// sm_100 PTX — tcgen05 is not available at this PTX target). 3-term bf16
// hi/lo split for fp32-grade accuracy. Persistent CTAs; W1 staged to smem
// once; A gathered per tile with register prefetch + double-buffered smem.

#define NODE_DIM 128
#define HID      64
#define TILE_M   128
#define NT       256

// smem byte offsets (A/B rows padded to 72 bf16 = 144B for conflict-free ldmatrix)
#define SM_B1   0                    // 64 f32
#define SM_W2   256                  // 64 f32
#define SM_B2   512                  // 1 f32
#define SM_ZB   1024                 // 128*2 f32 = 1024B
#define SM_BHI  2048                 // 256*72*2 = 36864
#define SM_BLO  (SM_BHI + 36864)
#define SM_A    (SM_BLO + 36864)     // two A buffers followed
#define ABUF    36864                // hi 18432 + lo 18432
#define ALO_OFF 18432
#define SM_TOT  (SM_A + 2 * ABUF)    // 149504 bytes

#define PITCH   144                  // bytes per padded row (72 bf16)

__device__ __forceinline__ uint32_t smem_u32(const void* p) {
    uint32_t a;
    asm("{ .reg .u64 t; cvta.to.shared.u64 t, %1; cvt.u32.u64 %0, t; }"
        : "=r"(a) : "l"(p));
    return a;
}
__device__ __forceinline__ void ldsm_x4(uint32_t* r, uint32_t a) {
    asm volatile("ldmatrix.sync.aligned.m8n8.x4.shared.b16 {%0,%1,%2,%3}, [%4];"
                 : "=r"(r[0]), "=r"(r[1]), "=r"(r[2]), "=r"(r[3]) : "r"(a));
}
__device__ __forceinline__ void ldsm_x2t(uint32_t* r, uint32_t a) {
    asm volatile("ldmatrix.sync.aligned.m8n8.x2.trans.shared.b16 {%0,%1}, [%2];"
                 : "=r"(r[0]), "=r"(r[1]) : "r"(a));
}
__device__ __forceinline__ void mma16816(float* d, const uint32_t* a,
                                         const uint32_t* b) {
    asm volatile(
        "mma.sync.aligned.m16n8k16.row.col.f32.bf16.bf16.f32 "
        "{%0,%1,%2,%3},{%4,%5,%6,%7},{%8,%9},{%0,%1,%2,%3};"
        : "+f"(d[0]), "+f"(d[1]), "+f"(d[2]), "+f"(d[3])
        : "r"(a[0]), "r"(a[1]), "r"(a[2]), "r"(a[3]), "r"(b[0]), "r"(b[1]));
}
__device__ __forceinline__ uint32_t pack_hi(float a, float b, uint32_t& lo) {
    __nv_bfloat162 h = __floats2bfloat162_rn(a, b);
    float2 hf = __bfloat1622float2(h);
    __nv_bfloat162 l = __floats2bfloat162_rn(a - hf.x, b - hf.y);
    lo = *reinterpret_cast<uint32_t*>(&l);
    return *reinterpret_cast<uint32_t*>(&h);
}

__global__ __launch_bounds__(NT, 1)
void edge_mlp_mma(const float* __restrict__ x,
                  const int*   __restrict__ ei,
                  const float* __restrict__ W1,
                  const float* __restrict__ b1,
                  const float* __restrict__ W2,
                  const float* __restrict__ b2,
                  float* __restrict__ out,
                  int E, int ntiles) {
    extern __shared__ char sm[];
    const uint32_t smb = smem_u32(sm);
    const int tid  = threadIdx.x;
    const int lane = tid & 31, wid = tid >> 5;
    const int wm = wid & 3, wn = wid >> 2;   // warp tile: 32 edges x 32 cols

    // ---- stage B = W1 (k-major 256x64) as bf16 hi/lo, 144B row pitch ----
    for (int idx = tid; idx < 2 * NODE_DIM * HID; idx += NT) {
        int kk = idx >> 6, nn = idx & 63;
        float v = W1[idx];
        __nv_bfloat16 h = __float2bfloat16(v);
        __nv_bfloat16 l = __float2bfloat16(v - __bfloat162float(h));
        uint32_t off = kk * PITCH + nn * 2;
        *reinterpret_cast<__nv_bfloat16*>(sm + SM_BHI + off) = h;
        *reinterpret_cast<__nv_bfloat16*>(sm + SM_BLO + off) = l;
    }
    if (tid < HID) {
        reinterpret_cast<float*>(sm + SM_B1)[tid] = b1[tid];
        reinterpret_cast<float*>(sm + SM_W2)[tid] = W2[tid];
    }
    if (tid == 0) reinterpret_cast<float*>(sm + SM_B2)[0] = b2[0];
    __syncthreads();

    const float bias2 = reinterpret_cast<float*>(sm + SM_B2)[0];
    const float* sB1 = reinterpret_cast<float*>(sm + SM_B1);
    const float* sW2 = reinterpret_cast<float*>(sm + SM_W2);
    float* sZB = reinterpret_cast<float*>(sm + SM_ZB);

    // per-lane ldmatrix address components
    const uint32_t aoff = (uint32_t)(lane & 15) * PITCH + (uint32_t)(lane >> 4) * 16;
    const uint32_t boff = (uint32_t)(lane & 15) * PITCH;

    const int e_loc = tid >> 1;          // gather role: edge within tile
    const int hhalf = tid & 1;           // which 32-float half of a 64-col chunk

    for (int tile = blockIdx.x; tile < ntiles; tile += gridDim.x) {
        // node indices for this thread's gather row
        int eg = tile * TILE_M + e_loc;
        int ec = (eg < E) ? eg : 0;
        int nd0 = ei[ec], nd1 = ei[E + ec];

        float d[2][4][4];
        #pragma unroll
        for (int i = 0; i < 2; i++)
            #pragma unroll
            for (int j = 0; j < 4; j++)
                #pragma unroll
                for (int q = 0; q < 4; q++) d[i][j][q] = 0.0f;

        // ---- prologue: gather chunk 0 -> buf0 ----
        {
            const float4* p = reinterpret_cast<const float4*>(
                x + (size_t)nd0 * NODE_DIM) + hhalf * 8;
            float4 v[8];
            #pragma unroll
            for (int i = 0; i < 8; i++) v[i] = p[i];
            char* base = sm + SM_A + e_loc * PITCH + hhalf * 64;
            #pragma unroll
            for (int g = 0; g < 4; g++) {
                float4 a = v[2 * g], b = v[2 * g + 1];
                uint32_t l0, l1, l2, l3;
                uint32_t h0 = pack_hi(a.x, a.y, l0);
                uint32_t h1 = pack_hi(a.z, a.w, l1);
                uint32_t h2 = pack_hi(b.x, b.y, l2);
                uint32_t h3 = pack_hi(b.z, b.w, l3);
                *reinterpret_cast<uint4*>(base + g * 16) = make_uint4(h0, h1, h2, h3);
                *reinterpret_cast<uint4*>(base + ALO_OFF + g * 16) =
                    make_uint4(l0, l1, l2, l3);
            }
        }

        // ---- main: 4 chunks of K=64, double-buffered ----
        #pragma unroll
        for (int c = 0; c < 4; c++) {
            __syncthreads();
            // prefetch next chunk while this chunk's MMAs run
            float4 v[8];
            if (c < 3) {
                int node = ((c + 1) >> 1) ? nd1 : nd0;
                int seg = (c + 1) & 1;
                const float4* p = reinterpret_cast<const float4*>(
                    x + (size_t)node * NODE_DIM + seg * 64) + hhalf * 8;
                #pragma unroll
                for (int i = 0; i < 8; i++) v[i] = p[i];
            }

            // MMA on chunk c from buf[c&1]
            {
                const uint32_t aHi = smb + SM_A + (c & 1) * ABUF + wm * 32 * PITCH;
                const uint32_t aLo = aHi + ALO_OFF;
                const uint32_t bHi = smb + SM_BHI + c * 64 * PITCH + wn * 32 * 2;
                const uint32_t bLo = bHi + 36864;
                #pragma unroll
                for (int ks = 0; ks < 4; ks++) {
                    uint32_t ah[2][4], al[2][4];
                    #pragma unroll
                    for (int mi = 0; mi < 2; mi++) {
                        uint32_t ao = mi * 16 * PITCH + aoff + ks * 32;
                        ldsm_x4(ah[mi], aHi + ao);
                        ldsm_x4(al[mi], aLo + ao);
                    }
                    #pragma unroll
                    for (int ni = 0; ni < 4; ni++) {
                        uint32_t bh[2], bl[2];
                        uint32_t bo = ks * 16 * PITCH + boff + ni * 16;
                        ldsm_x2t(bh, bHi + bo);
                        ldsm_x2t(bl, bLo + bo);
                        #pragma unroll
                        for (int mi = 0; mi < 2; mi++) {
                            mma16816(d[mi][ni], ah[mi], bh);
                            mma16816(d[mi][ni], al[mi], bh);
                            mma16816(d[mi][ni], ah[mi], bl);
                        }
                    }
                }
            }

            // store prefetched chunk c+1 into the other buffer
            if (c < 3) {
                char* base = sm + SM_A + ((c + 1) & 1) * ABUF + e_loc * PITCH +
                             hhalf * 64;
                #pragma unroll
                for (int g = 0; g < 4; g++) {
                    float4 a = v[2 * g], b = v[2 * g + 1];
                    uint32_t l0, l1, l2, l3;
                    uint32_t h0 = pack_hi(a.x, a.y, l0);
                    uint32_t h1 = pack_hi(a.z, a.w, l1);
                    uint32_t h2 = pack_hi(b.x, b.y, l2);
                    uint32_t h3 = pack_hi(b.z, b.w, l3);
                    *reinterpret_cast<uint4*>(base + g * 16) =
                        make_uint4(h0, h1, h2, h3);
                    *reinterpret_cast<uint4*>(base + ALO_OFF + g * 16) =
                        make_uint4(l0, l1, l2, l3);
                }
            }
        }

        // ---- epilogue: relu(d + b1) . W2, cross-lane + cross-warp reduce ----
        float zacc[2][2] = {{0.f, 0.f}, {0.f, 0.f}};
        #pragma unroll
        for (int mi = 0; mi < 2; mi++) {
            #pragma unroll
            for (int ni = 0; ni < 4; ni++) {
                int c0 = wn * 32 + ni * 8 + (lane & 3) * 2;
                float b1a = sB1[c0], b1b = sB1[c0 + 1];
                float w2a = sW2[c0], w2b = sW2[c0 + 1];
                float* dd = d[mi][ni];
                zacc[mi][0] = fmaf(fmaxf(dd[0] + b1a, 0.f), w2a, zacc[mi][0]);
                zacc[mi][0] = fmaf(fmaxf(dd[1] + b1b, 0.f), w2b, zacc[mi][0]);
                zacc[mi][1] = fmaf(fmaxf(dd[2] + b1a, 0.f), w2a, zacc[mi][1]);
                zacc[mi][1] = fmaf(fmaxf(dd[3] + b1b, 0.f), w2b, zacc[mi][1]);
            }
        }
        #pragma unroll
        for (int mi = 0; mi < 2; mi++)
            #pragma unroll
            for (int rh = 0; rh < 2; rh++) {
                float z = zacc[mi][rh];
                z += __shfl_xor_sync(0xFFFFFFFF, z, 1);
                z += __shfl_xor_sync(0xFFFFFFFF, z, 2);
                if ((lane & 3) == 0) {
                    int r = wm * 32 + mi * 16 + (lane >> 2) + rh * 8;
                    sZB[r * 2 + wn] = z;
                }
            }
        __syncthreads();
        if (tid < TILE_M) {
            float z = sZB[tid * 2] + sZB[tid * 2 + 1] + bias2;
            int ep = tile * TILE_M + tid;
            if (ep < E) out[ep] = 1.0f / (1.0f + __expf(-z));
        }
    }
}

extern "C" void kernel_launch(void* const* d_in, const int* in_sizes, int n_in,
                              void* d_out, int out_size) {
    const float* x  = (const float*)d_in[0];
    const int*   ei = (const int*)  d_in[1];
    const float* W1 = (const float*)d_in[2];
    const float* b1 = (const float*)d_in[3];
    const float* W2 = (const float*)d_in[4];
    const float* b2 = (const float*)d_in[5];
    float* out = (float*)d_out;

    const int E = out_size;
    const int ntiles = (E + TILE_M - 1) / TILE_M;

    cudaFuncSetAttribute(edge_mlp_mma,
                         cudaFuncAttributeMaxDynamicSharedMemorySize, SM_TOT);
    int grid = ntiles < 148 ? ntiles : 148;
    edge_mlp_mma<<<grid, NT, SM_TOT>>>(x, ei, W1, b1, W2, b2, out, E, ntiles);
}

// round 4
// speedup vs baseline: 11.1160x; 4.5764x over previous
#include <cuda_runtime.h>
#include <cuda_bf16.h>
#include <cstdint>

// Edge-MLP, factored:
//   H[n] = [ x[n] @ W1[0:128] | x[n] @ W1[128:256] ]   (node GEMM, tensor cores)
//   out[e] = sigmoid( relu(H[r][0:64] + H[c][64:128] + b1) . W2 + b2 )
// Kernel 1: (n_nodes x 128) @ (128 x 128) bf16 mma.sync, 3-term hi/lo split.
// Kernel 2: per-edge gather of two 256B rows from L2-resident H + tiny fp32 MLP.

#define NODE_DIM 128
#define HID      64
#define HOUT     128         // combined H width
#define MAXN     50176       // static scratch capacity (>= n_nodes)

__device__ float g_H[(size_t)MAXN * HOUT];

// ---------------- GEMM kernel (tile 128 x 128, K = 128) ----------------
#define GPITCH 272           // smem row pitch bytes (136 bf16) — conflict-free ldmatrix
#define SA_HI  0
#define SA_LO  34816         // 128 * 272
#define SB_HI  69632
#define SB_LO  104448
#define SMEM_G 139264

__device__ __forceinline__ uint32_t smem_u32(const void* p) {
    uint32_t a;
    asm("{ .reg .u64 t; cvta.to.shared.u64 t, %1; cvt.u32.u64 %0, t; }"
        : "=r"(a) : "l"(p));
    return a;
}
__device__ __forceinline__ void ldsm_x4(uint32_t* r, uint32_t a) {
    asm volatile("ldmatrix.sync.aligned.m8n8.x4.shared.b16 {%0,%1,%2,%3}, [%4];"
                 : "=r"(r[0]), "=r"(r[1]), "=r"(r[2]), "=r"(r[3]) : "r"(a));
}
__device__ __forceinline__ void ldsm_x2t(uint32_t* r, uint32_t a) {
    asm volatile("ldmatrix.sync.aligned.m8n8.x2.trans.shared.b16 {%0,%1}, [%2];"
                 : "=r"(r[0]), "=r"(r[1]) : "r"(a));
}
__device__ __forceinline__ void mma16816(float* d, const uint32_t* a,
                                         const uint32_t* b) {
    asm volatile(
        "mma.sync.aligned.m16n8k16.row.col.f32.bf16.bf16.f32 "
        "{%0,%1,%2,%3},{%4,%5,%6,%7},{%8,%9},{%0,%1,%2,%3};"
        : "+f"(d[0]), "+f"(d[1]), "+f"(d[2]), "+f"(d[3])
        : "r"(a[0]), "r"(a[1]), "r"(a[2]), "r"(a[3]), "r"(b[0]), "r"(b[1]));
}
__device__ __forceinline__ uint32_t pack_hi(float a, float b, uint32_t& lo) {
    __nv_bfloat162 h = __floats2bfloat162_rn(a, b);
    float2 hf = __bfloat1622float2(h);
    __nv_bfloat162 l = __floats2bfloat162_rn(a - hf.x, b - hf.y);
    lo = *reinterpret_cast<uint32_t*>(&l);
    return *reinterpret_cast<uint32_t*>(&h);
}

__global__ __launch_bounds__(256, 1)
void node_gemm(const float* __restrict__ x,
               const float* __restrict__ W1,
               int n_nodes, int ntiles) {
    extern __shared__ char sm[];
    const uint32_t smb = smem_u32(sm);
    const int tid = threadIdx.x, lane = tid & 31, wid = tid >> 5;
    const int wm = wid & 3, wn = wid >> 2;   // warp: 32 rows x 64 cols

    // stage B[k][j] = (j<64 ? W1[k][j] : W1[128+k][j-64]) as bf16 hi/lo
    for (int idx = tid; idx < NODE_DIM * HOUT; idx += 256) {
        int kk = idx >> 7, jj = idx & 127;
        float v = (jj < HID) ? W1[kk * HID + jj]
                             : W1[(NODE_DIM + kk) * HID + (jj - HID)];
        __nv_bfloat16 h = __float2bfloat16(v);
        __nv_bfloat16 l = __float2bfloat16(v - __bfloat162float(h));
        uint32_t off = kk * GPITCH + jj * 2;
        *reinterpret_cast<__nv_bfloat16*>(sm + SB_HI + off) = h;
        *reinterpret_cast<__nv_bfloat16*>(sm + SB_LO + off) = l;
    }

    const uint32_t aoff = (uint32_t)(lane & 15) * GPITCH + (uint32_t)(lane >> 4) * 16;
    const uint32_t boff = (uint32_t)(lane & 15) * GPITCH;

    for (int t = blockIdx.x; t < ntiles; t += gridDim.x) {
        const int m0 = t * 128;
        // ---- load A tile (128 x 128 f32, coalesced), convert hi/lo ----
        {
            int r = tid >> 1;
            int rr = m0 + r; if (rr >= n_nodes) rr = n_nodes - 1;
            const float4* src =
                reinterpret_cast<const float4*>(x + (size_t)rr * NODE_DIM) +
                (tid & 1) * 16;
            char* dh = sm + SA_HI + r * GPITCH + (tid & 1) * 128;
            char* dl = sm + SA_LO + r * GPITCH + (tid & 1) * 128;
            #pragma unroll
            for (int i = 0; i < 16; i++) {
                float4 v = src[i];
                uint32_t l0, l1;
                uint32_t h0 = pack_hi(v.x, v.y, l0);
                uint32_t h1 = pack_hi(v.z, v.w, l1);
                *reinterpret_cast<uint2*>(dh + i * 8) = make_uint2(h0, h1);
                *reinterpret_cast<uint2*>(dl + i * 8) = make_uint2(l0, l1);
            }
        }
        __syncthreads();

        // ---- MMA: 8 ksteps, warp tile 32x64, 3-term split ----
        float d[2][8][4];
        #pragma unroll
        for (int mi = 0; mi < 2; mi++)
            #pragma unroll
            for (int ni = 0; ni < 8; ni++)
                #pragma unroll
                for (int q = 0; q < 4; q++) d[mi][ni][q] = 0.0f;

        const uint32_t aHi = smb + SA_HI + wm * 32 * GPITCH;
        const uint32_t aLo = smb + SA_LO + wm * 32 * GPITCH;
        const uint32_t bHi = smb + SB_HI + wn * 64 * 2;
        const uint32_t bLo = smb + SB_LO + wn * 64 * 2;
        #pragma unroll
        for (int ks = 0; ks < 8; ks++) {
            uint32_t ah[2][4], al[2][4];
            #pragma unroll
            for (int mi = 0; mi < 2; mi++) {
                uint32_t ao = mi * 16 * GPITCH + ks * 32 + aoff;
                ldsm_x4(ah[mi], aHi + ao);
                ldsm_x4(al[mi], aLo + ao);
            }
            #pragma unroll
            for (int ni = 0; ni < 8; ni++) {
                uint32_t bh[2], bl[2];
                uint32_t bo = ks * 16 * GPITCH + boff + ni * 16;
                ldsm_x2t(bh, bHi + bo);
                ldsm_x2t(bl, bLo + bo);
                #pragma unroll
                for (int mi = 0; mi < 2; mi++) {
                    mma16816(d[mi][ni], ah[mi], bh);
                    mma16816(d[mi][ni], al[mi], bh);
                    mma16816(d[mi][ni], ah[mi], bl);
                }
            }
        }
        __syncthreads();   // smem reusable next iteration

        // ---- epilogue: write H tile ----
        #pragma unroll
        for (int mi = 0; mi < 2; mi++) {
            int mA = m0 + wm * 32 + mi * 16 + (lane >> 2);
            #pragma unroll
            for (int ni = 0; ni < 8; ni++) {
                int c = wn * 64 + ni * 8 + (lane & 3) * 2;
                if (mA < n_nodes)
                    *reinterpret_cast<float2*>(g_H + (size_t)mA * HOUT + c) =
                        make_float2(d[mi][ni][0], d[mi][ni][1]);
                if (mA + 8 < n_nodes)
                    *reinterpret_cast<float2*>(g_H + (size_t)(mA + 8) * HOUT + c) =
                        make_float2(d[mi][ni][2], d[mi][ni][3]);
            }
        }
    }
}

// ---------------- edge kernel: 4 threads per edge ----------------
__global__ __launch_bounds__(256)
void edge_eval(const int* __restrict__ ei,
               const float* __restrict__ b1,
               const float* __restrict__ W2,
               const float* __restrict__ b2,
               float* __restrict__ out,
               int E) {
    const int tid = threadIdx.x, lane = tid & 31, wid = tid >> 5;
    const int sub = lane & 3;                  // column quarter [sub*16, +16)
    const int qid = wid * 8 + (lane >> 2);     // edge slot in block: 0..63

    float b1r[16], w2r[16];
    #pragma unroll
    for (int i = 0; i < 16; i++) {
        b1r[i] = b1[sub * 16 + i];
        w2r[i] = W2[sub * 16 + i];
    }
    const float bias2 = b2[0];

    for (int eb = blockIdx.x * 64; eb < E; eb += gridDim.x * 64) {
        int e = eb + qid;
        bool valid = e < E;
        int es = valid ? e : 0;
        int r0 = 0, c0 = 0;
        if (sub == 0) { r0 = ei[es]; c0 = ei[E + es]; }
        r0 = __shfl_sync(0xFFFFFFFF, r0, lane & ~3);
        c0 = __shfl_sync(0xFFFFFFFF, c0, lane & ~3);

        const float4* p1 =
            reinterpret_cast<const float4*>(g_H + (size_t)r0 * HOUT) + sub * 4;
        const float4* p2 =
            reinterpret_cast<const float4*>(g_H + (size_t)c0 * HOUT + HID) + sub * 4;

        float z = 0.0f;
        #pragma unroll
        for (int i = 0; i < 4; i++) {
            float4 a = p1[i];
            float4 b = p2[i];
            z = fmaf(fmaxf(a.x + b.x + b1r[4 * i + 0], 0.f), w2r[4 * i + 0], z);
            z = fmaf(fmaxf(a.y + b.y + b1r[4 * i + 1], 0.f), w2r[4 * i + 1], z);
            z = fmaf(fmaxf(a.z + b.z + b1r[4 * i + 2], 0.f), w2r[4 * i + 2], z);
            z = fmaf(fmaxf(a.w + b.w + b1r[4 * i + 3], 0.f), w2r[4 * i + 3], z);
        }
        z += __shfl_xor_sync(0xFFFFFFFF, z, 1);
        z += __shfl_xor_sync(0xFFFFFFFF, z, 2);
        if (sub == 0 && valid)
            out[e] = 1.0f / (1.0f + __expf(-(z + bias2)));
    }
}

extern "C" void kernel_launch(void* const* d_in, const int* in_sizes, int n_in,
                              void* d_out, int out_size) {
    const float* x  = (const float*)d_in[0];
    const int*   ei = (const int*)  d_in[1];
    const float* W1 = (const float*)d_in[2];
    const float* b1 = (const float*)d_in[3];
    const float* W2 = (const float*)d_in[4];
    const float* b2 = (const float*)d_in[5];
    float* out = (float*)d_out;

    const int E = out_size;
    int n_nodes = in_sizes[0] / NODE_DIM;
    if (n_nodes > MAXN) n_nodes = MAXN;
    const int ntiles = (n_nodes + 127) / 128;

    cudaFuncSetAttribute(node_gemm,
                         cudaFuncAttributeMaxDynamicSharedMemorySize, SMEM_G);

    int g1 = ntiles < 148 ? ntiles : 148;
    node_gemm<<<g1, 256, SMEM_G>>>(x, W1, n_nodes, ntiles);

    edge_eval<<<1184, 256>>>(ei, b1, W2, b2, out, E);
}

// round 5
// speedup vs baseline: 14.1529x; 1.2732x over previous
#include <cuda_runtime.h>
#include <cuda_bf16.h>
#include <cuda_fp16.h>
#include <cstdint>

// Edge-MLP, factored:
//   H[n] = [ x[n] @ W1[0:128] | x[n] @ W1[128:256] ]   (node GEMM, tensor cores)
//   out[e] = sigmoid( relu(H[r][0:64] + H[c][64:128] + b1) . W2 + b2 )
// H stored fp16 (each 64-col half = one 128B line). Edge kernel: 8 threads/edge,
// 16B/thread -> 1 L1 wavefront per line, L2-byte bound.

#define NODE_DIM 128
#define HID      64
#define HOUT     128
#define MAXN     50176

__device__ __half g_H2[(size_t)MAXN * HOUT];

// ---------------- GEMM kernel (tile 128 x 128, K = 128) ----------------
#define GPITCH 272
#define SA_HI  0
#define SA_LO  34816
#define SB_HI  69632
#define SB_LO  104448
#define SMEM_G 139264

__device__ __forceinline__ uint32_t smem_u32(const void* p) {
    uint32_t a;
    asm("{ .reg .u64 t; cvta.to.shared.u64 t, %1; cvt.u32.u64 %0, t; }"
        : "=r"(a) : "l"(p));
    return a;
}
__device__ __forceinline__ void ldsm_x4(uint32_t* r, uint32_t a) {
    asm volatile("ldmatrix.sync.aligned.m8n8.x4.shared.b16 {%0,%1,%2,%3}, [%4];"
                 : "=r"(r[0]), "=r"(r[1]), "=r"(r[2]), "=r"(r[3]) : "r"(a));
}
__device__ __forceinline__ void ldsm_x2t(uint32_t* r, uint32_t a) {
    asm volatile("ldmatrix.sync.aligned.m8n8.x2.trans.shared.b16 {%0,%1}, [%2];"
                 : "=r"(r[0]), "=r"(r[1]) : "r"(a));
}
__device__ __forceinline__ void mma16816(float* d, const uint32_t* a,
                                         const uint32_t* b) {
    asm volatile(
        "mma.sync.aligned.m16n8k16.row.col.f32.bf16.bf16.f32 "
        "{%0,%1,%2,%3},{%4,%5,%6,%7},{%8,%9},{%0,%1,%2,%3};"
        : "+f"(d[0]), "+f"(d[1]), "+f"(d[2]), "+f"(d[3])
        : "r"(a[0]), "r"(a[1]), "r"(a[2]), "r"(a[3]), "r"(b[0]), "r"(b[1]));
}
__device__ __forceinline__ uint32_t pack_hi(float a, float b, uint32_t& lo) {
    __nv_bfloat162 h = __floats2bfloat162_rn(a, b);
    float2 hf = __bfloat1622float2(h);
    __nv_bfloat162 l = __floats2bfloat162_rn(a - hf.x, b - hf.y);
    lo = *reinterpret_cast<uint32_t*>(&l);
    return *reinterpret_cast<uint32_t*>(&h);
}

__global__ __launch_bounds__(256, 1)
void node_gemm(const float* __restrict__ x,
               const float* __restrict__ W1,
               int n_nodes, int ntiles) {
    extern __shared__ char sm[];
    const uint32_t smb = smem_u32(sm);
    const int tid = threadIdx.x, lane = tid & 31, wid = tid >> 5;
    const int wm = wid & 3, wn = wid >> 2;   // warp: 32 rows x 64 cols

    // stage B[k][j] = (j<64 ? W1[k][j] : W1[128+k][j-64]) as bf16 hi/lo
    for (int idx = tid; idx < NODE_DIM * HOUT; idx += 256) {
        int kk = idx >> 7, jj = idx & 127;
        float v = (jj < HID) ? W1[kk * HID + jj]
                             : W1[(NODE_DIM + kk) * HID + (jj - HID)];
        __nv_bfloat16 h = __float2bfloat16(v);
        __nv_bfloat16 l = __float2bfloat16(v - __bfloat162float(h));
        uint32_t off = kk * GPITCH + jj * 2;
        *reinterpret_cast<__nv_bfloat16*>(sm + SB_HI + off) = h;
        *reinterpret_cast<__nv_bfloat16*>(sm + SB_LO + off) = l;
    }

    const uint32_t aoff = (uint32_t)(lane & 15) * GPITCH + (uint32_t)(lane >> 4) * 16;
    const uint32_t boff = (uint32_t)(lane & 15) * GPITCH;

    for (int t = blockIdx.x; t < ntiles; t += gridDim.x) {
        const int m0 = t * 128;
        // ---- load A tile (128 x 128 f32, coalesced), convert hi/lo ----
        {
            int r = tid >> 1;
            int rr = m0 + r; if (rr >= n_nodes) rr = n_nodes - 1;
            const float4* src =
                reinterpret_cast<const float4*>(x + (size_t)rr * NODE_DIM) +
                (tid & 1) * 16;
            char* dh = sm + SA_HI + r * GPITCH + (tid & 1) * 128;
            char* dl = sm + SA_LO + r * GPITCH + (tid & 1) * 128;
            #pragma unroll
            for (int i = 0; i < 16; i++) {
                float4 v = src[i];
                uint32_t l0, l1;
                uint32_t h0 = pack_hi(v.x, v.y, l0);
                uint32_t h1 = pack_hi(v.z, v.w, l1);
                *reinterpret_cast<uint2*>(dh + i * 8) = make_uint2(h0, h1);
                *reinterpret_cast<uint2*>(dl + i * 8) = make_uint2(l0, l1);
            }
        }
        __syncthreads();

        // ---- MMA: 8 ksteps, warp tile 32x64, 3-term split ----
        float d[2][8][4];
        #pragma unroll
        for (int mi = 0; mi < 2; mi++)
            #pragma unroll
            for (int ni = 0; ni < 8; ni++)
                #pragma unroll
                for (int q = 0; q < 4; q++) d[mi][ni][q] = 0.0f;

        const uint32_t aHi = smb + SA_HI + wm * 32 * GPITCH;
        const uint32_t aLo = smb + SA_LO + wm * 32 * GPITCH;
        const uint32_t bHi = smb + SB_HI + wn * 64 * 2;
        const uint32_t bLo = smb + SB_LO + wn * 64 * 2;
        #pragma unroll
        for (int ks = 0; ks < 8; ks++) {
            uint32_t ah[2][4], al[2][4];
            #pragma unroll
            for (int mi = 0; mi < 2; mi++) {
                uint32_t ao = mi * 16 * GPITCH + ks * 32 + aoff;
                ldsm_x4(ah[mi], aHi + ao);
                ldsm_x4(al[mi], aLo + ao);
            }
            #pragma unroll
            for (int ni = 0; ni < 8; ni++) {
                uint32_t bh[2], bl[2];
                uint32_t bo = ks * 16 * GPITCH + boff + ni * 16;
                ldsm_x2t(bh, bHi + bo);
                ldsm_x2t(bl, bLo + bo);
                #pragma unroll
                for (int mi = 0; mi < 2; mi++) {
                    mma16816(d[mi][ni], ah[mi], bh);
                    mma16816(d[mi][ni], al[mi], bh);
                    mma16816(d[mi][ni], ah[mi], bl);
                }
            }
        }
        __syncthreads();

        // ---- epilogue: write H tile as fp16 ----
        #pragma unroll
        for (int mi = 0; mi < 2; mi++) {
            int mA = m0 + wm * 32 + mi * 16 + (lane >> 2);
            #pragma unroll
            for (int ni = 0; ni < 8; ni++) {
                int c = wn * 64 + ni * 8 + (lane & 3) * 2;
                if (mA < n_nodes) {
                    __half2 hv = __floats2half2_rn(d[mi][ni][0], d[mi][ni][1]);
                    *reinterpret_cast<__half2*>(g_H2 + (size_t)mA * HOUT + c) = hv;
                }
                if (mA + 8 < n_nodes) {
                    __half2 hv = __floats2half2_rn(d[mi][ni][2], d[mi][ni][3]);
                    *reinterpret_cast<__half2*>(g_H2 + (size_t)(mA + 8) * HOUT + c) = hv;
                }
            }
        }
    }
}

// ---------------- edge kernel: 8 threads per edge, fp16 H ----------------
__global__ __launch_bounds__(256)
void edge_eval(const int* __restrict__ ei,
               const float* __restrict__ b1,
               const float* __restrict__ W2,
               const float* __restrict__ b2,
               float* __restrict__ out,
               int E) {
    const int tid = threadIdx.x, lane = tid & 31, wid = tid >> 5;
    const int sub  = lane & 7;     // this thread's 8-col slice [sub*8, +8)
    const int slot = lane >> 3;    // edge 0..3 within warp

    float b1r[8], w2r[8];
    #pragma unroll
    for (int i = 0; i < 8; i++) {
        b1r[i] = b1[sub * 8 + i];
        w2r[i] = W2[sub * 8 + i];
    }
    const float bias2 = b2[0];

    for (int eb = blockIdx.x * 32 + wid * 4; eb < E; eb += gridDim.x * 32) {
        int e = eb + slot;
        bool valid = e < E;
        int es = valid ? e : 0;
        int r0 = 0, c0 = 0;
        if (sub == 0) { r0 = ei[es]; c0 = ei[E + es]; }
        r0 = __shfl_sync(0xFFFFFFFF, r0, lane & 24);
        c0 = __shfl_sync(0xFFFFFFFF, c0, lane & 24);

        const uint4* pa =
            reinterpret_cast<const uint4*>(g_H2 + (size_t)r0 * HOUT) + sub;
        const uint4* pb =
            reinterpret_cast<const uint4*>(g_H2 + (size_t)c0 * HOUT + HID) + sub;
        uint4 av = *pa;
        uint4 bv = *pb;

        const __half2* ah = reinterpret_cast<const __half2*>(&av);
        const __half2* bh = reinterpret_cast<const __half2*>(&bv);
        float z = 0.0f;
        #pragma unroll
        for (int j = 0; j < 4; j++) {
            float2 fa = __half22float2(ah[j]);
            float2 fb = __half22float2(bh[j]);
            z = fmaf(fmaxf(fa.x + fb.x + b1r[2 * j],     0.f), w2r[2 * j],     z);
            z = fmaf(fmaxf(fa.y + fb.y + b1r[2 * j + 1], 0.f), w2r[2 * j + 1], z);
        }
        z += __shfl_xor_sync(0xFFFFFFFF, z, 1);
        z += __shfl_xor_sync(0xFFFFFFFF, z, 2);
        z += __shfl_xor_sync(0xFFFFFFFF, z, 4);
        if (sub == 0 && valid)
            out[e] = 1.0f / (1.0f + __expf(-(z + bias2)));
    }
}

extern "C" void kernel_launch(void* const* d_in, const int* in_sizes, int n_in,
                              void* d_out, int out_size) {
    const float* x  = (const float*)d_in[0];
    const int*   ei = (const int*)  d_in[1];
    const float* W1 = (const float*)d_in[2];
    const float* b1 = (const float*)d_in[3];
    const float* W2 = (const float*)d_in[4];
    const float* b2 = (const float*)d_in[5];
    float* out = (float*)d_out;

    const int E = out_size;
    int n_nodes = in_sizes[0] / NODE_DIM;
    if (n_nodes > MAXN) n_nodes = MAXN;
    const int ntiles = (n_nodes + 127) / 128;

    cudaFuncSetAttribute(node_gemm,
                         cudaFuncAttributeMaxDynamicSharedMemorySize, SMEM_G);

    int g1 = ntiles < 148 ? ntiles : 148;
    node_gemm<<<g1, 256, SMEM_G>>>(x, W1, n_nodes, ntiles);

    edge_eval<<<1184, 256>>>(ei, b1, W2, b2, out, E);
}

// round 6
// speedup vs baseline: 18.1819x; 1.2847x over previous
#include <cuda_runtime.h>
#include <cuda_bf16.h>
#include <cuda_fp16.h>
#include <cstdint>

// Edge-MLP, factored:
//   H[n] = [ x[n]@W1[0:128] + b1 | x[n]@W1[128:256] ]   (node GEMM, tensor cores)
//   out[e] = sigmoid( relu(H[r][0:64] + H[c][64:128]) . W2 + b2 )
// H fp16 (each half = one 128B line, b1 folded into first half).
// Edge kernel: 8 threads/edge, 4 edges per group-iteration, batched loads.

#define NODE_DIM 128
#define HID      64
#define HOUT     128
#define MAXN     50176

__device__ __half g_H2[(size_t)MAXN * HOUT];

// ---------------- GEMM kernel (tile 128 x 128, K = 128) ----------------
#define GPITCH 272
#define SA_HI  0
#define SA_LO  34816
#define SB_HI  69632
#define SB_LO  104448
#define SMEM_G 139264

__device__ __forceinline__ uint32_t smem_u32(const void* p) {
    uint32_t a;
    asm("{ .reg .u64 t; cvta.to.shared.u64 t, %1; cvt.u32.u64 %0, t; }"
        : "=r"(a) : "l"(p));
    return a;
}
__device__ __forceinline__ void ldsm_x4(uint32_t* r, uint32_t a) {
    asm volatile("ldmatrix.sync.aligned.m8n8.x4.shared.b16 {%0,%1,%2,%3}, [%4];"
                 : "=r"(r[0]), "=r"(r[1]), "=r"(r[2]), "=r"(r[3]) : "r"(a));
}
__device__ __forceinline__ void ldsm_x2t(uint32_t* r, uint32_t a) {
    asm volatile("ldmatrix.sync.aligned.m8n8.x2.trans.shared.b16 {%0,%1}, [%2];"
                 : "=r"(r[0]), "=r"(r[1]) : "r"(a));
}
__device__ __forceinline__ void mma16816(float* d, const uint32_t* a,
                                         const uint32_t* b) {
    asm volatile(
        "mma.sync.aligned.m16n8k16.row.col.f32.bf16.bf16.f32 "
        "{%0,%1,%2,%3},{%4,%5,%6,%7},{%8,%9},{%0,%1,%2,%3};"
        : "+f"(d[0]), "+f"(d[1]), "+f"(d[2]), "+f"(d[3])
        : "r"(a[0]), "r"(a[1]), "r"(a[2]), "r"(a[3]), "r"(b[0]), "r"(b[1]));
}
__device__ __forceinline__ uint32_t pack_hi(float a, float b, uint32_t& lo) {
    __nv_bfloat162 h = __floats2bfloat162_rn(a, b);
    float2 hf = __bfloat1622float2(h);
    __nv_bfloat162 l = __floats2bfloat162_rn(a - hf.x, b - hf.y);
    lo = *reinterpret_cast<uint32_t*>(&l);
    return *reinterpret_cast<uint32_t*>(&h);
}

__global__ __launch_bounds__(256, 1)
void node_gemm(const float* __restrict__ x,
               const float* __restrict__ W1,
               const float* __restrict__ b1,
               int n_nodes, int ntiles) {
    extern __shared__ char sm[];
    const uint32_t smb = smem_u32(sm);
    const int tid = threadIdx.x, lane = tid & 31, wid = tid >> 5;
    const int wm = wid & 3, wn = wid >> 2;   // warp: 32 rows x 64 cols

    for (int idx = tid; idx < NODE_DIM * HOUT; idx += 256) {
        int kk = idx >> 7, jj = idx & 127;
        float v = (jj < HID) ? W1[kk * HID + jj]
                             : W1[(NODE_DIM + kk) * HID + (jj - HID)];
        __nv_bfloat16 h = __float2bfloat16(v);
        __nv_bfloat16 l = __float2bfloat16(v - __bfloat162float(h));
        uint32_t off = kk * GPITCH + jj * 2;
        *reinterpret_cast<__nv_bfloat16*>(sm + SB_HI + off) = h;
        *reinterpret_cast<__nv_bfloat16*>(sm + SB_LO + off) = l;
    }

    const uint32_t aoff = (uint32_t)(lane & 15) * GPITCH + (uint32_t)(lane >> 4) * 16;
    const uint32_t boff = (uint32_t)(lane & 15) * GPITCH;

    for (int t = blockIdx.x; t < ntiles; t += gridDim.x) {
        const int m0 = t * 128;
        {
            int r = tid >> 1;
            int rr = m0 + r; if (rr >= n_nodes) rr = n_nodes - 1;
            const float4* src =
                reinterpret_cast<const float4*>(x + (size_t)rr * NODE_DIM) +
                (tid & 1) * 16;
            char* dh = sm + SA_HI + r * GPITCH + (tid & 1) * 128;
            char* dl = sm + SA_LO + r * GPITCH + (tid & 1) * 128;
            #pragma unroll
            for (int i = 0; i < 16; i++) {
                float4 v = src[i];
                uint32_t l0, l1;
                uint32_t h0 = pack_hi(v.x, v.y, l0);
                uint32_t h1 = pack_hi(v.z, v.w, l1);
                *reinterpret_cast<uint2*>(dh + i * 8) = make_uint2(h0, h1);
                *reinterpret_cast<uint2*>(dl + i * 8) = make_uint2(l0, l1);
            }
        }
        __syncthreads();

        float d[2][8][4];
        #pragma unroll
        for (int mi = 0; mi < 2; mi++)
            #pragma unroll
            for (int ni = 0; ni < 8; ni++)
                #pragma unroll
                for (int q = 0; q < 4; q++) d[mi][ni][q] = 0.0f;

        const uint32_t aHi = smb + SA_HI + wm * 32 * GPITCH;
        const uint32_t aLo = smb + SA_LO + wm * 32 * GPITCH;
        const uint32_t bHi = smb + SB_HI + wn * 64 * 2;
        const uint32_t bLo = smb + SB_LO + wn * 64 * 2;
        #pragma unroll
        for (int ks = 0; ks < 8; ks++) {
            uint32_t ah[2][4], al[2][4];
            #pragma unroll
            for (int mi = 0; mi < 2; mi++) {
                uint32_t ao = mi * 16 * GPITCH + ks * 32 + aoff;
                ldsm_x4(ah[mi], aHi + ao);
                ldsm_x4(al[mi], aLo + ao);
            }
            #pragma unroll
            for (int ni = 0; ni < 8; ni++) {
                uint32_t bh[2], bl[2];
                uint32_t bo = ks * 16 * GPITCH + boff + ni * 16;
                ldsm_x2t(bh, bHi + bo);
                ldsm_x2t(bl, bLo + bo);
                #pragma unroll
                for (int mi = 0; mi < 2; mi++) {
                    mma16816(d[mi][ni], ah[mi], bh);
                    mma16816(d[mi][ni], al[mi], bh);
                    mma16816(d[mi][ni], ah[mi], bl);
                }
            }
        }
        __syncthreads();

        // ---- epilogue: (+ b1 on first half), write H tile as fp16 ----
        #pragma unroll
        for (int mi = 0; mi < 2; mi++) {
            int mA = m0 + wm * 32 + mi * 16 + (lane >> 2);
            #pragma unroll
            for (int ni = 0; ni < 8; ni++) {
                int c = wn * 64 + ni * 8 + (lane & 3) * 2;
                float d0 = d[mi][ni][0], d1 = d[mi][ni][1];
                float d2 = d[mi][ni][2], d3 = d[mi][ni][3];
                if (wn == 0) {
                    float2 bb = *reinterpret_cast<const float2*>(b1 + c);
                    d0 += bb.x; d1 += bb.y; d2 += bb.x; d3 += bb.y;
                }
                if (mA < n_nodes)
                    *reinterpret_cast<__half2*>(g_H2 + (size_t)mA * HOUT + c) =
                        __floats2half2_rn(d0, d1);
                if (mA + 8 < n_nodes)
                    *reinterpret_cast<__half2*>(g_H2 + (size_t)(mA + 8) * HOUT + c) =
                        __floats2half2_rn(d2, d3);
            }
        }
    }
}

// -------- edge kernel: 8 threads/edge, 4 edges per group iteration --------
__global__ __launch_bounds__(256, 4)
void edge_eval(const int* __restrict__ ei,
               const float* __restrict__ W2,
               const float* __restrict__ b2,
               float* __restrict__ out,
               int E) {
    const int tid = threadIdx.x, lane = tid & 31, wid = tid >> 5;
    const int sub = lane & 7;          // 8-col slice [sub*8, +8)
    const int grp = lane >> 3;         // group 0..3 in warp

    float w2r[8];
    #pragma unroll
    for (int i = 0; i < 8; i++) w2r[i] = __ldg(W2 + sub * 8 + i);
    const float bias2 = __ldg(b2);

    const int stride = gridDim.x * 128;
    for (int eb = blockIdx.x * 128 + wid * 16 + grp * 4; eb < E; eb += stride) {
        // 4 edges' indices: one int4 broadcast load each (E % 4 == 0 path)
        int4 rv, cv;
        if (eb + 4 <= E) {
            rv = __ldg(reinterpret_cast<const int4*>(ei + eb));
            cv = __ldg(reinterpret_cast<const int4*>(ei + E + eb));
        } else {
            int* rp = &rv.x; int* cp = &cv.x;
            #pragma unroll
            for (int j = 0; j < 4; j++) {
                int e = eb + j < E ? eb + j : E - 1;
                rp[j] = __ldg(ei + e);
                cp[j] = __ldg(ei + E + e);
            }
        }
        const int* rp = &rv.x;
        const int* cp = &cv.x;

        // batched H loads: 8 independent 16B loads in flight
        uint4 av[4], bv[4];
        #pragma unroll
        for (int j = 0; j < 4; j++) {
            av[j] = __ldg(reinterpret_cast<const uint4*>(
                        g_H2 + (size_t)rp[j] * HOUT) + sub);
            bv[j] = __ldg(reinterpret_cast<const uint4*>(
                        g_H2 + (size_t)cp[j] * HOUT + HID) + sub);
        }

        float z[4];
        #pragma unroll
        for (int j = 0; j < 4; j++) {
            const __half2* ah = reinterpret_cast<const __half2*>(&av[j]);
            const __half2* bh = reinterpret_cast<const __half2*>(&bv[j]);
            float zz = 0.0f;
            #pragma unroll
            for (int q = 0; q < 4; q++) {
                __half2 s = __hmax2(__hadd2(ah[q], bh[q]),
                                    __half2(__half(0), __half(0)));
                float2 f = __half22float2(s);
                zz = fmaf(f.x, w2r[2 * q],     zz);
                zz = fmaf(f.y, w2r[2 * q + 1], zz);
            }
            z[j] = zz;
        }
        #pragma unroll
        for (int j = 0; j < 4; j++) {
            z[j] += __shfl_xor_sync(0xFFFFFFFF, z[j], 1);
            z[j] += __shfl_xor_sync(0xFFFFFFFF, z[j], 2);
            z[j] += __shfl_xor_sync(0xFFFFFFFF, z[j], 4);
        }
        if (sub == 0) {
            #pragma unroll
            for (int j = 0; j < 4; j++) {
                if (eb + j < E)
                    out[eb + j] = 1.0f / (1.0f + __expf(-(z[j] + bias2)));
            }
        }
    }
}

extern "C" void kernel_launch(void* const* d_in, const int* in_sizes, int n_in,
                              void* d_out, int out_size) {
    const float* x  = (const float*)d_in[0];
    const int*   ei = (const int*)  d_in[1];
    const float* W1 = (const float*)d_in[2];
    const float* b1 = (const float*)d_in[3];
    const float* W2 = (const float*)d_in[4];
    const float* b2 = (const float*)d_in[5];
    float* out = (float*)d_out;

    const int E = out_size;
    int n_nodes = in_sizes[0] / NODE_DIM;
    if (n_nodes > MAXN) n_nodes = MAXN;
    const int ntiles = (n_nodes + 127) / 128;

    cudaFuncSetAttribute(node_gemm,
                         cudaFuncAttributeMaxDynamicSharedMemorySize, SMEM_G);

    int g1 = ntiles < 148 ? ntiles : 148;
    node_gemm<<<g1, 256, SMEM_G>>>(x, W1, b1, n_nodes, ntiles);

    edge_eval<<<592, 256>>>(ei, W2, b2, out, E);
}

// round 7
// speedup vs baseline: 20.8155x; 1.1448x over previous
#include <cuda_runtime.h>
#include <cuda_fp16.h>
#include <cstdint>

// Edge-MLP, factored:
//   H[n] = [ x[n]@W1[0:128] + b1 | x[n]@W1[128:256] ]   (node GEMM, tensor cores)
//   out[e] = sigmoid( relu(H[r][0:64] + H[c][64:128]) . W2 + b2 )
// GEMM: fp16 2-term split (A = Ah+Al fp16, B single fp16), mma.sync m16n8k16,
// register double-buffered A-tile loads. H fp16, b1 folded.
// Edge kernel: 8 threads/edge, 4 edges per group-iteration, batched loads.

#define NODE_DIM 128
#define HID      64
#define HOUT     128
#define MAXN     50176

__device__ __half g_H2[(size_t)MAXN * HOUT];

// ---------------- GEMM kernel (tile 128 x 128, K = 128) ----------------
#define GPITCH 272           // 136 halfs per row — conflict-free ldmatrix
#define SA_HI  0
#define SA_LO  34816
#define SB     69632
#define SMEM_G 104448

__device__ __forceinline__ uint32_t smem_u32(const void* p) {
    uint32_t a;
    asm("{ .reg .u64 t; cvta.to.shared.u64 t, %1; cvt.u32.u64 %0, t; }"
        : "=r"(a) : "l"(p));
    return a;
}
__device__ __forceinline__ void ldsm_x4(uint32_t* r, uint32_t a) {
    asm volatile("ldmatrix.sync.aligned.m8n8.x4.shared.b16 {%0,%1,%2,%3}, [%4];"
                 : "=r"(r[0]), "=r"(r[1]), "=r"(r[2]), "=r"(r[3]) : "r"(a));
}
__device__ __forceinline__ void ldsm_x2t(uint32_t* r, uint32_t a) {
    asm volatile("ldmatrix.sync.aligned.m8n8.x2.trans.shared.b16 {%0,%1}, [%2];"
                 : "=r"(r[0]), "=r"(r[1]) : "r"(a));
}
__device__ __forceinline__ void mma16816h(float* d, const uint32_t* a,
                                          const uint32_t* b) {
    asm volatile(
        "mma.sync.aligned.m16n8k16.row.col.f32.f16.f16.f32 "
        "{%0,%1,%2,%3},{%4,%5,%6,%7},{%8,%9},{%0,%1,%2,%3};"
        : "+f"(d[0]), "+f"(d[1]), "+f"(d[2]), "+f"(d[3])
        : "r"(a[0]), "r"(a[1]), "r"(a[2]), "r"(a[3]), "r"(b[0]), "r"(b[1]));
}
// fp16 hi/lo split pack: hi of (a,b) and lo of (a,b) as packed half2 words
__device__ __forceinline__ uint32_t pack_hi_h(float a, float b, uint32_t& lo) {
    __half ha = __float2half_rn(a), hb = __float2half_rn(b);
    __half la = __float2half_rn(a - __half2float(ha));
    __half lb = __float2half_rn(b - __half2float(hb));
    __half2 h = __halves2half2(ha, hb);
    __half2 l = __halves2half2(la, lb);
    lo = *reinterpret_cast<uint32_t*>(&l);
    return *reinterpret_cast<uint32_t*>(&h);
}

__global__ __launch_bounds__(256, 1)
void node_gemm(const float* __restrict__ x,
               const float* __restrict__ W1,
               const float* __restrict__ b1,
               int n_nodes, int ntiles) {
    extern __shared__ char sm[];
    const uint32_t smb = smem_u32(sm);
    const int tid = threadIdx.x, lane = tid & 31, wid = tid >> 5;
    const int wm = wid & 3, wn = wid >> 2;   // warp: 32 rows x 64 cols

    // stage B[k][j] = (j<64 ? W1[k][j] : W1[128+k][j-64]) as single fp16
    for (int idx = tid; idx < NODE_DIM * HOUT; idx += 256) {
        int kk = idx >> 7, jj = idx & 127;
        float v = (jj < HID) ? W1[kk * HID + jj]
                             : W1[(NODE_DIM + kk) * HID + (jj - HID)];
        *reinterpret_cast<__half*>(sm + SB + kk * GPITCH + jj * 2) =
            __float2half_rn(v);
    }

    const uint32_t aoff = (uint32_t)(lane & 15) * GPITCH + (uint32_t)(lane >> 4) * 16;
    const uint32_t boff = (uint32_t)(lane & 15) * GPITCH;
    const int r_loc = tid >> 1, seg = tid & 1;   // A-load role

    // ---- stage first tile ----
    int t = blockIdx.x;
    bool have = t < ntiles;
    if (have) {
        int rr = t * 128 + r_loc; if (rr >= n_nodes) rr = n_nodes - 1;
        const float4* src =
            reinterpret_cast<const float4*>(x + (size_t)rr * NODE_DIM) + seg * 16;
        char* dh = sm + SA_HI + r_loc * GPITCH + seg * 128;
        char* dl = sm + SA_LO + r_loc * GPITCH + seg * 128;
        #pragma unroll
        for (int i = 0; i < 16; i++) {
            float4 v = src[i];
            uint32_t l0, l1;
            uint32_t h0 = pack_hi_h(v.x, v.y, l0);
            uint32_t h1 = pack_hi_h(v.z, v.w, l1);
            *reinterpret_cast<uint2*>(dh + i * 8) = make_uint2(h0, h1);
            *reinterpret_cast<uint2*>(dl + i * 8) = make_uint2(l0, l1);
        }
    }

    while (have) {
        const int tn = t + (int)gridDim.x;
        const bool haveN = tn < ntiles;
        __syncthreads();                 // current tile staged & visible

        // prefetch next tile's A rows into registers (hides under MMA)
        float4 v[16];
        if (haveN) {
            int rr = tn * 128 + r_loc; if (rr >= n_nodes) rr = n_nodes - 1;
            const float4* src =
                reinterpret_cast<const float4*>(x + (size_t)rr * NODE_DIM) +
                seg * 16;
            #pragma unroll
            for (int i = 0; i < 16; i++) v[i] = src[i];
        }

        // ---- MMA: 8 ksteps, warp tile 32x64, 2-term fp16 split ----
        float d[2][8][4];
        #pragma unroll
        for (int mi = 0; mi < 2; mi++)
            #pragma unroll
            for (int ni = 0; ni < 8; ni++)
                #pragma unroll
                for (int q = 0; q < 4; q++) d[mi][ni][q] = 0.0f;

        const uint32_t aHi = smb + SA_HI + wm * 32 * GPITCH;
        const uint32_t aLo = smb + SA_LO + wm * 32 * GPITCH;
        const uint32_t bB  = smb + SB + wn * 64 * 2;
        #pragma unroll
        for (int ks = 0; ks < 8; ks++) {
            uint32_t ah[2][4], al[2][4];
            #pragma unroll
            for (int mi = 0; mi < 2; mi++) {
                uint32_t ao = mi * 16 * GPITCH + ks * 32 + aoff;
                ldsm_x4(ah[mi], aHi + ao);
                ldsm_x4(al[mi], aLo + ao);
            }
            #pragma unroll
            for (int ni = 0; ni < 8; ni++) {
                uint32_t bh[2];
                ldsm_x2t(bh, bB + ks * 16 * GPITCH + boff + ni * 16);
                #pragma unroll
                for (int mi = 0; mi < 2; mi++) {
                    mma16816h(d[mi][ni], ah[mi], bh);
                    mma16816h(d[mi][ni], al[mi], bh);
                }
            }
        }
        __syncthreads();                 // all warps done reading smem

        // store prefetched tile into smem (next iteration's operand)
        if (haveN) {
            char* dh = sm + SA_HI + r_loc * GPITCH + seg * 128;
            char* dl = sm + SA_LO + r_loc * GPITCH + seg * 128;
            #pragma unroll
            for (int i = 0; i < 16; i++) {
                uint32_t l0, l1;
                uint32_t h0 = pack_hi_h(v[i].x, v[i].y, l0);
                uint32_t h1 = pack_hi_h(v[i].z, v[i].w, l1);
                *reinterpret_cast<uint2*>(dh + i * 8) = make_uint2(h0, h1);
                *reinterpret_cast<uint2*>(dl + i * 8) = make_uint2(l0, l1);
            }
        }

        // ---- epilogue: (+ b1 on first half), write H tile as fp16 ----
        const int m0 = t * 128;
        #pragma unroll
        for (int mi = 0; mi < 2; mi++) {
            int mA = m0 + wm * 32 + mi * 16 + (lane >> 2);
            #pragma unroll
            for (int ni = 0; ni < 8; ni++) {
                int c = wn * 64 + ni * 8 + (lane & 3) * 2;
                float d0 = d[mi][ni][0], d1 = d[mi][ni][1];
                float d2 = d[mi][ni][2], d3 = d[mi][ni][3];
                if (wn == 0) {
                    float2 bb = *reinterpret_cast<const float2*>(b1 + c);
                    d0 += bb.x; d1 += bb.y; d2 += bb.x; d3 += bb.y;
                }
                if (mA < n_nodes)
                    *reinterpret_cast<__half2*>(g_H2 + (size_t)mA * HOUT + c) =
                        __floats2half2_rn(d0, d1);
                if (mA + 8 < n_nodes)
                    *reinterpret_cast<__half2*>(g_H2 + (size_t)(mA + 8) * HOUT + c) =
                        __floats2half2_rn(d2, d3);
            }
        }
        t = tn; have = haveN;
    }
}

// -------- edge kernel: 8 threads/edge, 4 edges per group iteration --------
__global__ __launch_bounds__(256, 4)
void edge_eval(const int* __restrict__ ei,
               const float* __restrict__ W2,
               const float* __restrict__ b2,
               float* __restrict__ out,
               int E) {
    const int tid = threadIdx.x, lane = tid & 31, wid = tid >> 5;
    const int sub = lane & 7;
    const int grp = lane >> 3;

    float w2r[8];
    #pragma unroll
    for (int i = 0; i < 8; i++) w2r[i] = __ldg(W2 + sub * 8 + i);
    const float bias2 = __ldg(b2);

    const int stride = gridDim.x * 128;
    for (int eb = blockIdx.x * 128 + wid * 16 + grp * 4; eb < E; eb += stride) {
        int4 rv, cv;
        if (eb + 4 <= E) {
            rv = __ldg(reinterpret_cast<const int4*>(ei + eb));
            cv = __ldg(reinterpret_cast<const int4*>(ei + E + eb));
        } else {
            int* rp = &rv.x; int* cp = &cv.x;
            #pragma unroll
            for (int j = 0; j < 4; j++) {
                int e = eb + j < E ? eb + j : E - 1;
                rp[j] = __ldg(ei + e);
                cp[j] = __ldg(ei + E + e);
            }
        }
        const int* rp = &rv.x;
        const int* cp = &cv.x;

        uint4 av[4], bv[4];
        #pragma unroll
        for (int j = 0; j < 4; j++) {
            av[j] = __ldg(reinterpret_cast<const uint4*>(
                        g_H2 + (size_t)rp[j] * HOUT) + sub);
            bv[j] = __ldg(reinterpret_cast<const uint4*>(
                        g_H2 + (size_t)cp[j] * HOUT + HID) + sub);
        }

        float z[4];
        #pragma unroll
        for (int j = 0; j < 4; j++) {
            const __half2* ah = reinterpret_cast<const __half2*>(&av[j]);
            const __half2* bh = reinterpret_cast<const __half2*>(&bv[j]);
            float zz = 0.0f;
            #pragma unroll
            for (int q = 0; q < 4; q++) {
                __half2 s = __hmax2(__hadd2(ah[q], bh[q]),
                                    __half2(__half(0), __half(0)));
                float2 f = __half22float2(s);
                zz = fmaf(f.x, w2r[2 * q],     zz);
                zz = fmaf(f.y, w2r[2 * q + 1], zz);
            }
            z[j] = zz;
        }
        #pragma unroll
        for (int j = 0; j < 4; j++) {
            z[j] += __shfl_xor_sync(0xFFFFFFFF, z[j], 1);
            z[j] += __shfl_xor_sync(0xFFFFFFFF, z[j], 2);
            z[j] += __shfl_xor_sync(0xFFFFFFFF, z[j], 4);
        }
        if (sub == 0) {
            #pragma unroll
            for (int j = 0; j < 4; j++) {
                if (eb + j < E)
                    out[eb + j] = 1.0f / (1.0f + __expf(-(z[j] + bias2)));
            }
        }
    }
}

extern "C" void kernel_launch(void* const* d_in, const int* in_sizes, int n_in,
                              void* d_out, int out_size) {
    const float* x  = (const float*)d_in[0];
    const int*   ei = (const int*)  d_in[1];
    const float* W1 = (const float*)d_in[2];
    const float* b1 = (const float*)d_in[3];
    const float* W2 = (const float*)d_in[4];
    const float* b2 = (const float*)d_in[5];
    float* out = (float*)d_out;

    const int E = out_size;
    int n_nodes = in_sizes[0] / NODE_DIM;
    if (n_nodes > MAXN) n_nodes = MAXN;
    const int ntiles = (n_nodes + 127) / 128;

    cudaFuncSetAttribute(node_gemm,
                         cudaFuncAttributeMaxDynamicSharedMemorySize, SMEM_G);

    int g1 = ntiles < 148 ? ntiles : 148;
    node_gemm<<<g1, 256, SMEM_G>>>(x, W1, b1, n_nodes, ntiles);

    edge_eval<<<592, 256>>>(ei, W2, b2, out, E);
}